// round 9
// baseline (speedup 1.0000x reference)
#include <cuda_runtime.h>
#include <math.h>
#include <stdint.h>

#define NLVL 16
#define TSIZE (1u << 19)
#define TMASK (TSIZE - 1u)
#define HPRIME 2654435761u

#define NPTS_MAX 2097152
#define NBUCK 65536

__device__ uint32_t g_hist[NBUCK];
__device__ uint32_t g_cursor[NBUCK];
__device__ uint32_t g_perm[NPTS_MAX];

// fragment-packed tf32-rounded weights: L1 40x64 (5kt x 8nt), L2 64x64 (8x8), L3 64x8 (8x1)
#define B1_F 0
#define B2_F 2560
#define B3_F 6656
#define WPACKF 7168
__device__ float g_wfrag[WPACKF];

#define SA_STRIDE 68
#define SA_BASE 7168
#define NWARP 8
#define SMEM_FLOATS (SA_BASE + NWARP * 32 * SA_STRIDE)   // 24576
#define SMEM_BYTES (SMEM_FLOATS * 4)

struct LevelParams {
    float resf[NLVL];
    int   res1[NLVL];
    int   dense[NLVL];
};

// ---------------- Morton helpers ----------------
__device__ __forceinline__ uint32_t part1by1(uint32_t x) {
    x &= 0xFFu;
    x = (x | (x << 4)) & 0x0F0Fu;
    x = (x | (x << 2)) & 0x3333u;
    x = (x | (x << 1)) & 0x5555u;
    return x;
}
__device__ __forceinline__ uint32_t bucket_code(float px, float py) {
    int bx = (int)(px * 256.0f); bx = bx < 0 ? 0 : (bx > 255 ? 255 : bx);
    int by = (int)(py * 256.0f); by = by < 0 ? 0 : (by > 255 ? 255 : by);
    return part1by1((uint32_t)bx) | (part1by1((uint32_t)by) << 1);
}

// ---------------- fused setup: zero hist + pack tf32 weights ----------------
__global__ void setup_kernel(const float* __restrict__ w1,
                             const float* __restrict__ w2,
                             const float* __restrict__ w3) {
    int b = blockIdx.x;
    int t = threadIdx.x;
    if (b < 256) {
        g_hist[b * 256 + t] = 0u;
        return;
    }
    int e = (b - 256) * 256 + t;
    if (e >= WPACKF) return;
    int base, NT, rel;
    const float* W; int ncols; int kmax;
    if (e < B2_F)      { base = B1_F; NT = 8; rel = e - B1_F; W = w1; ncols = 64; kmax = 34; }
    else if (e < B3_F) { base = B2_F; NT = 8; rel = e - B2_F; W = w2; ncols = 64; kmax = 64; }
    else               { base = B3_F; NT = 1; rel = e - B3_F; W = w3; ncols = 3;  kmax = 64; }
    int tile = rel >> 6;
    int r    = rel & 63;
    int lane = r >> 1, sel = r & 1;
    int kt = tile / NT, nt = tile % NT;
    int k = kt * 8 + (lane & 3) + sel * 4;
    int n = nt * 8 + (lane >> 2);
    float v = 0.0f;
    if (k < kmax && n < ncols) v = W[k * ncols + n];
    uint32_t hb;
    asm("cvt.rna.tf32.f32 %0, %1;" : "=r"(hb) : "f"(v));
    g_wfrag[e] = __uint_as_float(hb);
}

// ---------------- hist / scan / scatter (4 pts per thread, R6 form) ----------------
__global__ void hist_kernel(const float4* __restrict__ xin4, int npts) {
    int t = blockIdx.x * 256 + threadIdx.x;
    int i0 = t * 4;
    if (i0 >= npts) return;
    float4 a = __ldg(xin4 + t * 2);
    float4 b = __ldg(xin4 + t * 2 + 1);
    atomicAdd(&g_hist[bucket_code(a.x, a.y)], 1u);
    if (i0 + 1 < npts) atomicAdd(&g_hist[bucket_code(a.z, a.w)], 1u);
    if (i0 + 2 < npts) atomicAdd(&g_hist[bucket_code(b.x, b.y)], 1u);
    if (i0 + 3 < npts) atomicAdd(&g_hist[bucket_code(b.z, b.w)], 1u);
}

__global__ __launch_bounds__(1024) void scan_kernel() {
    __shared__ uint32_t sh[1024];
    const int t = threadIdx.x;
    uint32_t loc[64];
    uint32_t sum = 0;
#pragma unroll
    for (int j = 0; j < 64; j++) { loc[j] = sum; sum += g_hist[t * 64 + j]; }
    sh[t] = sum;
    __syncthreads();
    for (int d = 1; d < 1024; d <<= 1) {
        uint32_t v = (t >= d) ? sh[t - d] : 0u;
        __syncthreads();
        sh[t] += v;
        __syncthreads();
    }
    uint32_t base = sh[t] - sum;
#pragma unroll
    for (int j = 0; j < 64; j++) g_cursor[t * 64 + j] = base + loc[j];
}

__global__ void scatter_kernel(const float4* __restrict__ xin4, int npts) {
    int t = blockIdx.x * 256 + threadIdx.x;
    int i0 = t * 4;
    if (i0 >= npts) return;
    float4 a = __ldg(xin4 + t * 2);
    float4 b = __ldg(xin4 + t * 2 + 1);
    uint32_t s0 = atomicAdd(&g_cursor[bucket_code(a.x, a.y)], 1u);
    g_perm[s0] = (uint32_t)i0;
    if (i0 + 1 < npts) { uint32_t s = atomicAdd(&g_cursor[bucket_code(a.z, a.w)], 1u); g_perm[s] = (uint32_t)(i0 + 1); }
    if (i0 + 2 < npts) { uint32_t s = atomicAdd(&g_cursor[bucket_code(b.x, b.y)], 1u); g_perm[s] = (uint32_t)(i0 + 2); }
    if (i0 + 3 < npts) { uint32_t s = atomicAdd(&g_cursor[bucket_code(b.z, b.w)], 1u); g_perm[s] = (uint32_t)(i0 + 3); }
}

// ---------------- mma helpers ----------------
__device__ __forceinline__ void cvt_hilo(float v, uint32_t& h, uint32_t& l) {
    uint32_t hb;
    asm("cvt.rna.tf32.f32 %0, %1;" : "=r"(hb) : "f"(v));
    h = hb;
    l = __float_as_uint(v - __uint_as_float(hb));
}
__device__ __forceinline__ void mma8(float c[4], const uint32_t a[4], const uint32_t b[2]) {
    asm volatile("mma.sync.aligned.m16n8k8.row.col.f32.tf32.tf32.f32 "
        "{%0,%1,%2,%3}, {%4,%5,%6,%7}, {%8,%9}, {%0,%1,%2,%3};"
        : "+f"(c[0]), "+f"(c[1]), "+f"(c[2]), "+f"(c[3])
        : "r"(a[0]), "r"(a[1]), "r"(a[2]), "r"(a[3]), "r"(b[0]), "r"(b[1]));
}

template<int KT, int NT>
__device__ __forceinline__ void mma_layer(const float* __restrict__ sB,
                                          const float* __restrict__ sA,
                                          float C[2][NT][4], int lane) {
    const int g = lane >> 2, c = lane & 3;
#pragma unroll
    for (int mt = 0; mt < 2; mt++)
#pragma unroll
        for (int nt = 0; nt < NT; nt++)
#pragma unroll
            for (int r = 0; r < 4; r++) C[mt][nt][r] = 0.0f;

#pragma unroll 1
    for (int kt = 0; kt < KT; kt++) {
        uint32_t Bh[NT][2];
#pragma unroll
        for (int nt = 0; nt < NT; nt++) {
            float2 bv = *(const float2*)(sB + (kt * NT + nt) * 64 + lane * 2);
            Bh[nt][0] = __float_as_uint(bv.x);   // pre-rounded tf32
            Bh[nt][1] = __float_as_uint(bv.y);
        }
#pragma unroll
        for (int mt = 0; mt < 2; mt++) {
            const float* ar = sA + (mt * 16 + g) * SA_STRIDE + kt * 8;
            uint32_t Ah[4], Al[4];
            cvt_hilo(ar[c],                     Ah[0], Al[0]);
            cvt_hilo(ar[8 * SA_STRIDE + c],     Ah[1], Al[1]);
            cvt_hilo(ar[c + 4],                 Ah[2], Al[2]);
            cvt_hilo(ar[8 * SA_STRIDE + c + 4], Ah[3], Al[3]);
#pragma unroll
            for (int nt = 0; nt < NT; nt++) {
                mma8(C[mt][nt], Ah, Bh[nt]);
                mma8(C[mt][nt], Al, Bh[nt]);
            }
        }
    }
}

template<int NT>
__device__ __forceinline__ void store_relu(float* __restrict__ sA,
                                           float C[2][NT][4], int lane) {
    const int g = lane >> 2, c = lane & 3;
#pragma unroll
    for (int mt = 0; mt < 2; mt++)
#pragma unroll
        for (int nt = 0; nt < NT; nt++) {
            float* p = sA + (mt * 16 + g) * SA_STRIDE + nt * 8 + 2 * c;
            *(float2*)p = make_float2(fmaxf(C[mt][nt][0], 0.f), fmaxf(C[mt][nt][1], 0.f));
            *(float2*)(p + 8 * SA_STRIDE) =
                make_float2(fmaxf(C[mt][nt][2], 0.f), fmaxf(C[mt][nt][3], 0.f));
        }
}

// ---------------- main fused persistent kernel ----------------
__global__ __launch_bounds__(256, 2)
void videohash_kernel(const float2* __restrict__ xin,
                      const float2* __restrict__ tables,
                      float* __restrict__ out,
                      int npts, int ntiles, LevelParams lp)
{
    extern __shared__ float smf[];

    const int tid  = threadIdx.x;
    const int warp = tid >> 5;
    const int lane = tid & 31;
    float* sA = smf + SA_BASE + warp * (32 * SA_STRIDE);

    // stage weights to SMEM ONCE per CTA (coalesced, 7 float4 per thread)
    {
        const float4* src = (const float4*)g_wfrag;
        float4* dst = (float4*)smf;
#pragma unroll
        for (int i = 0; i < 7; i++) dst[i * 256 + tid] = src[i * 256 + tid];
    }
    __syncthreads();   // weights visible to all warps; everything below is warp-autonomous

    for (int tile = blockIdx.x; tile < ntiles; tile += gridDim.x) {
        int slot = tile * 256 + tid;
        if (slot >= npts) slot = npts - 1;
        const int pid = (int)g_perm[slot];
        const float2 p = __ldg(xin + pid);

        // -------- encode --------
        float enc[36];
        enc[0] = p.x; enc[1] = p.y; enc[34] = 0.f; enc[35] = 0.f;
#pragma unroll
        for (int l = 0; l < NLVL; l++) {
            const float rf = lp.resf[l];
            float px = p.x * rf, py = p.y * rf;
            float fx = floorf(px), fy = floorf(py);
            float wx = px - fx, wy = py - fy;
            unsigned X = (unsigned)fx, Y = (unsigned)fy;
            const float2* tab = tables + (size_t)l * TSIZE;
            unsigned i00, i10, i01, i11;
            if (lp.dense[l]) {
                unsigned r1 = (unsigned)lp.res1[l];
                unsigned b = X + Y * r1;
                i00 = b; i10 = b + 1u; i01 = b + r1; i11 = b + r1 + 1u;
            } else {
                unsigned hy = Y * HPRIME, hy1 = (Y + 1u) * HPRIME;
                i00 = (X ^ hy)  & TMASK; i10 = ((X + 1u) ^ hy)  & TMASK;
                i01 = (X ^ hy1) & TMASK; i11 = ((X + 1u) ^ hy1) & TMASK;
            }
            float2 f00 = __ldg(tab + i00), f10 = __ldg(tab + i10);
            float2 f01 = __ldg(tab + i01), f11 = __ldg(tab + i11);
            float w00 = (1.f - wx) * (1.f - wy), w10 = wx * (1.f - wy);
            float w01 = (1.f - wx) * wy,         w11 = wx * wy;
            enc[2 + 2 * l]     = f00.x * w00 + f10.x * w10 + f01.x * w01 + f11.x * w11;
            enc[2 + 2 * l + 1] = f00.y * w00 + f10.y * w10 + f01.y * w01 + f11.y * w11;
        }

        // stage enc to A tile row = lane
        {
            float* row = sA + lane * SA_STRIDE;
#pragma unroll
            for (int j = 0; j < 9; j++)
                *(float4*)(row + 4 * j) =
                    make_float4(enc[4 * j], enc[4 * j + 1], enc[4 * j + 2], enc[4 * j + 3]);
            *(float4*)(row + 36) = make_float4(0.f, 0.f, 0.f, 0.f);
        }
        __syncwarp();

        // -------- layer 1: K=40, N=64 --------
        {
            float C[2][8][4];
            mma_layer<5, 8>(smf + B1_F, sA, C, lane);
            __syncwarp();
            store_relu<8>(sA, C, lane);
            __syncwarp();
        }
        // -------- layer 2: K=64, N=64 --------
        {
            float C[2][8][4];
            mma_layer<8, 8>(smf + B2_F, sA, C, lane);
            __syncwarp();
            store_relu<8>(sA, C, lane);
            __syncwarp();
        }
        // -------- layer 3: K=64, N=8 (3 valid) --------
        {
            float C[2][1][4];
            mma_layer<8, 1>(smf + B3_F, sA, C, lane);

            const int g = lane >> 2, c = lane & 3;
#pragma unroll
            for (int mt = 0; mt < 2; mt++) {
                int r0 = mt * 16 + g;
                int pa = __shfl_sync(0xFFFFFFFFu, pid, r0);
                int pb = __shfl_sync(0xFFFFFFFFu, pid, r0 + 8);
                if (c == 0) {
                    out[pa * 3 + 0] = C[mt][0][0];
                    out[pa * 3 + 1] = C[mt][0][1];
                    out[pb * 3 + 0] = C[mt][0][2];
                    out[pb * 3 + 1] = C[mt][0][3];
                } else if (c == 1) {
                    out[pa * 3 + 2] = C[mt][0][0];
                    out[pb * 3 + 2] = C[mt][0][2];
                }
            }
            __syncwarp();
        }
    }
}

extern "C" void kernel_launch(void* const* d_in, const int* in_sizes, int n_in,
                              void* d_out, int out_size)
{
    const float* x      = (const float*)d_in[0];
    const float* tables = (const float*)d_in[1];
    const float* w1     = (const float*)d_in[2];
    const float* w2     = (const float*)d_in[3];
    const float* w3     = (const float*)d_in[4];

    const int npts = in_sizes[0] / 2;

    LevelParams lp;
    for (int l = 0; l < NLVL; l++) {
        int res = (int)floor(16.0 * pow(1.3819, (double)l));
        lp.resf[l]  = (float)res;
        lp.res1[l]  = res + 1;
        long long dsz = (long long)(res + 1) * (long long)(res + 1);
        lp.dense[l] = (dsz <= (long long)TSIZE) ? 1 : 0;
    }

    cudaFuncSetAttribute(videohash_kernel,
                         cudaFuncAttributeMaxDynamicSharedMemorySize, SMEM_BYTES);

    const int nq = (npts + 3) / 4;
    const int nbq = (nq + 255) / 256;

    setup_kernel<<<256 + (WPACKF + 255) / 256, 256>>>(w1, w2, w3);
    hist_kernel<<<nbq, 256>>>((const float4*)x, npts);
    scan_kernel<<<1, 1024>>>();
    scatter_kernel<<<nbq, 256>>>((const float4*)x, npts);

    const int ntiles = (npts + 255) / 256;
    const int grid = 296;   // 2 CTAs per SM, persistent
    videohash_kernel<<<grid, 256, SMEM_BYTES>>>((const float2*)x, (const float2*)tables,
                                                (float*)d_out, npts, ntiles, lp);
}

// round 10
// speedup vs baseline: 1.0681x; 1.0681x over previous
#include <cuda_runtime.h>
#include <math.h>
#include <stdint.h>

#define NLVL 16
#define TSIZE (1u << 19)
#define TMASK (TSIZE - 1u)
#define HPRIME 2654435761u

#define NPTS_MAX 2097152
#define NBUCK 65536

__device__ uint32_t g_hist[NBUCK];
__device__ uint32_t g_cursor[NBUCK];
__device__ uint32_t g_perm[NPTS_MAX];

// fragment-packed tf32-rounded weights: L1 40x64 (5kt x 8nt), L2 64x64 (8x8), L3 64x8 (8x1)
#define B1_F 0
#define B2_F 2560
#define B3_F 6656
#define WPACKF 7168
__device__ float g_wfrag[WPACKF];

#define SA_STRIDE 68
#define SA_BASE 7168
#define NWARP 8
#define SMEM_FLOATS (SA_BASE + NWARP * 32 * SA_STRIDE)   // 24576
#define SMEM_BYTES (SMEM_FLOATS * 4)

struct LevelParams {
    float resf[NLVL];
    int   res1[NLVL];
    int   dense[NLVL];
};

// ---------------- Morton helpers ----------------
__device__ __forceinline__ uint32_t part1by1(uint32_t x) {
    x &= 0xFFu;
    x = (x | (x << 4)) & 0x0F0Fu;
    x = (x | (x << 2)) & 0x3333u;
    x = (x | (x << 1)) & 0x5555u;
    return x;
}
__device__ __forceinline__ uint32_t bucket_code(float px, float py) {
    int bx = (int)(px * 256.0f); bx = bx < 0 ? 0 : (bx > 255 ? 255 : bx);
    int by = (int)(py * 256.0f); by = by < 0 ? 0 : (by > 255 ? 255 : by);
    return part1by1((uint32_t)bx) | (part1by1((uint32_t)by) << 1);
}

// ---------------- fused setup: zero hist + pack tf32 weights ----------------
__global__ void setup_kernel(const float* __restrict__ w1,
                             const float* __restrict__ w2,
                             const float* __restrict__ w3) {
    int b = blockIdx.x;
    int t = threadIdx.x;
    if (b < 256) {
        g_hist[b * 256 + t] = 0u;
        return;
    }
    int e = (b - 256) * 256 + t;
    if (e >= WPACKF) return;
    int base, NT, rel;
    const float* W; int ncols; int kmax;
    if (e < B2_F)      { base = B1_F; NT = 8; rel = e - B1_F; W = w1; ncols = 64; kmax = 34; }
    else if (e < B3_F) { base = B2_F; NT = 8; rel = e - B2_F; W = w2; ncols = 64; kmax = 64; }
    else               { base = B3_F; NT = 1; rel = e - B3_F; W = w3; ncols = 3;  kmax = 64; }
    int tile = rel >> 6;
    int r    = rel & 63;
    int lane = r >> 1, sel = r & 1;
    int kt = tile / NT, nt = tile % NT;
    int k = kt * 8 + (lane & 3) + sel * 4;
    int n = nt * 8 + (lane >> 2);
    float v = 0.0f;
    if (k < kmax && n < ncols) v = W[k * ncols + n];
    uint32_t hb;
    asm("cvt.rna.tf32.f32 %0, %1;" : "=r"(hb) : "f"(v));
    g_wfrag[e] = __uint_as_float(hb);
}

// ---------------- hist / scan / scatter (4 pts per thread) ----------------
__global__ void hist_kernel(const float4* __restrict__ xin4, int npts) {
    int t = blockIdx.x * 256 + threadIdx.x;
    int i0 = t * 4;
    if (i0 >= npts) return;
    float4 a = __ldg(xin4 + t * 2);
    float4 b = __ldg(xin4 + t * 2 + 1);
    atomicAdd(&g_hist[bucket_code(a.x, a.y)], 1u);
    if (i0 + 1 < npts) atomicAdd(&g_hist[bucket_code(a.z, a.w)], 1u);
    if (i0 + 2 < npts) atomicAdd(&g_hist[bucket_code(b.x, b.y)], 1u);
    if (i0 + 3 < npts) atomicAdd(&g_hist[bucket_code(b.z, b.w)], 1u);
}

__global__ __launch_bounds__(1024) void scan_kernel() {
    __shared__ uint32_t sh[1024];
    const int t = threadIdx.x;
    uint32_t loc[64];
    uint32_t sum = 0;
#pragma unroll
    for (int j = 0; j < 64; j++) { loc[j] = sum; sum += g_hist[t * 64 + j]; }
    sh[t] = sum;
    __syncthreads();
    for (int d = 1; d < 1024; d <<= 1) {
        uint32_t v = (t >= d) ? sh[t - d] : 0u;
        __syncthreads();
        sh[t] += v;
        __syncthreads();
    }
    uint32_t base = sh[t] - sum;
#pragma unroll
    for (int j = 0; j < 64; j++) g_cursor[t * 64 + j] = base + loc[j];
}

__global__ void scatter_kernel(const float4* __restrict__ xin4, int npts) {
    int t = blockIdx.x * 256 + threadIdx.x;
    int i0 = t * 4;
    if (i0 >= npts) return;
    float4 a = __ldg(xin4 + t * 2);
    float4 b = __ldg(xin4 + t * 2 + 1);
    uint32_t s0 = atomicAdd(&g_cursor[bucket_code(a.x, a.y)], 1u);
    g_perm[s0] = (uint32_t)i0;
    if (i0 + 1 < npts) { uint32_t s = atomicAdd(&g_cursor[bucket_code(a.z, a.w)], 1u); g_perm[s] = (uint32_t)(i0 + 1); }
    if (i0 + 2 < npts) { uint32_t s = atomicAdd(&g_cursor[bucket_code(b.x, b.y)], 1u); g_perm[s] = (uint32_t)(i0 + 2); }
    if (i0 + 3 < npts) { uint32_t s = atomicAdd(&g_cursor[bucket_code(b.z, b.w)], 1u); g_perm[s] = (uint32_t)(i0 + 3); }
}

// ---------------- mma helpers ----------------
__device__ __forceinline__ void cvt_hilo(float v, uint32_t& h, uint32_t& l) {
    uint32_t hb;
    asm("cvt.rna.tf32.f32 %0, %1;" : "=r"(hb) : "f"(v));
    h = hb;
    l = __float_as_uint(v - __uint_as_float(hb));
}
__device__ __forceinline__ void mma8(float c[4], const uint32_t a[4], const uint32_t b[2]) {
    asm volatile("mma.sync.aligned.m16n8k8.row.col.f32.tf32.tf32.f32 "
        "{%0,%1,%2,%3}, {%4,%5,%6,%7}, {%8,%9}, {%0,%1,%2,%3};"
        : "+f"(c[0]), "+f"(c[1]), "+f"(c[2]), "+f"(c[3])
        : "r"(a[0]), "r"(a[1]), "r"(a[2]), "r"(a[3]), "r"(b[0]), "r"(b[1]));
}

template<int KT, int NT>
__device__ __forceinline__ void mma_layer(const float* __restrict__ sB,
                                          const float* __restrict__ sA,
                                          float C[2][NT][4], int lane) {
    const int g = lane >> 2, c = lane & 3;
#pragma unroll
    for (int mt = 0; mt < 2; mt++)
#pragma unroll
        for (int nt = 0; nt < NT; nt++)
#pragma unroll
            for (int r = 0; r < 4; r++) C[mt][nt][r] = 0.0f;

#pragma unroll 1
    for (int kt = 0; kt < KT; kt++) {
        uint32_t Bh[NT][2];
#pragma unroll
        for (int nt = 0; nt < NT; nt++) {
            float2 bv = *(const float2*)(sB + (kt * NT + nt) * 64 + lane * 2);
            Bh[nt][0] = __float_as_uint(bv.x);   // pre-rounded tf32
            Bh[nt][1] = __float_as_uint(bv.y);
        }
#pragma unroll
        for (int mt = 0; mt < 2; mt++) {
            const float* ar = sA + (mt * 16 + g) * SA_STRIDE + kt * 8;
            uint32_t Ah[4], Al[4];
            cvt_hilo(ar[c],                     Ah[0], Al[0]);
            cvt_hilo(ar[8 * SA_STRIDE + c],     Ah[1], Al[1]);
            cvt_hilo(ar[c + 4],                 Ah[2], Al[2]);
            cvt_hilo(ar[8 * SA_STRIDE + c + 4], Ah[3], Al[3]);
#pragma unroll
            for (int nt = 0; nt < NT; nt++) {
                mma8(C[mt][nt], Ah, Bh[nt]);
                mma8(C[mt][nt], Al, Bh[nt]);
            }
        }
    }
}

template<int NT>
__device__ __forceinline__ void store_relu(float* __restrict__ sA,
                                           float C[2][NT][4], int lane) {
    const int g = lane >> 2, c = lane & 3;
#pragma unroll
    for (int mt = 0; mt < 2; mt++)
#pragma unroll
        for (int nt = 0; nt < NT; nt++) {
            float* p = sA + (mt * 16 + g) * SA_STRIDE + nt * 8 + 2 * c;
            *(float2*)p = make_float2(fmaxf(C[mt][nt][0], 0.f), fmaxf(C[mt][nt][1], 0.f));
            *(float2*)(p + 8 * SA_STRIDE) =
                make_float2(fmaxf(C[mt][nt][2], 0.f), fmaxf(C[mt][nt][3], 0.f));
        }
}

// ---------------- main fused kernel ----------------
__global__ __launch_bounds__(256, 2)
void videohash_kernel(const float2* __restrict__ xin,
                      const float2* __restrict__ tables,
                      float* __restrict__ out,
                      int npts, LevelParams lp)
{
    extern __shared__ float smf[];

    const int tid  = threadIdx.x;
    const int warp = tid >> 5;
    const int lane = tid & 31;
    float* sA = smf + SA_BASE + warp * (32 * SA_STRIDE);

    // stage weights to SMEM (coalesced, 7 float4 per thread)
    {
        const float4* src = (const float4*)g_wfrag;
        float4* dst = (float4*)smf;
#pragma unroll
        for (int i = 0; i < 7; i++) dst[i * 256 + tid] = src[i * 256 + tid];
    }

    int slot = blockIdx.x * 256 + tid;
    if (slot >= npts) slot = npts - 1;
    const int pid = (int)g_perm[slot];
    const float2 p = __ldg(xin + pid);

    // -------- encode: 4 batches of 4 levels; issue 16 gathers, then consume --------
    float enc[36];
    enc[0] = p.x; enc[1] = p.y; enc[34] = 0.f; enc[35] = 0.f;
#pragma unroll
    for (int lb = 0; lb < 4; lb++) {
        float2 f[4][4];
        float wxv[4], wyv[4];
        // phase 1: indices + issue all 16 loads
#pragma unroll
        for (int l4 = 0; l4 < 4; l4++) {
            const int l = lb * 4 + l4;
            const float rf = lp.resf[l];
            float px = p.x * rf, py = p.y * rf;
            float fx = floorf(px), fy = floorf(py);
            wxv[l4] = px - fx; wyv[l4] = py - fy;
            unsigned X = (unsigned)fx, Y = (unsigned)fy;
            const float2* tab = tables + (size_t)l * TSIZE;
            unsigned i00, i10, i01, i11;
            if (lp.dense[l]) {
                unsigned r1 = (unsigned)lp.res1[l];
                unsigned b = X + Y * r1;
                i00 = b; i10 = b + 1u; i01 = b + r1; i11 = b + r1 + 1u;
            } else {
                unsigned hy = Y * HPRIME, hy1 = (Y + 1u) * HPRIME;
                i00 = (X ^ hy)  & TMASK; i10 = ((X + 1u) ^ hy)  & TMASK;
                i01 = (X ^ hy1) & TMASK; i11 = ((X + 1u) ^ hy1) & TMASK;
            }
            f[l4][0] = __ldg(tab + i00);
            f[l4][1] = __ldg(tab + i10);
            f[l4][2] = __ldg(tab + i01);
            f[l4][3] = __ldg(tab + i11);
        }
        // phase 2: interpolate
#pragma unroll
        for (int l4 = 0; l4 < 4; l4++) {
            const int l = lb * 4 + l4;
            float wx = wxv[l4], wy = wyv[l4];
            float w00 = (1.f - wx) * (1.f - wy), w10 = wx * (1.f - wy);
            float w01 = (1.f - wx) * wy,         w11 = wx * wy;
            enc[2 + 2 * l]     = f[l4][0].x * w00 + f[l4][1].x * w10
                               + f[l4][2].x * w01 + f[l4][3].x * w11;
            enc[2 + 2 * l + 1] = f[l4][0].y * w00 + f[l4][1].y * w10
                               + f[l4][2].y * w01 + f[l4][3].y * w11;
        }
    }

    // stage enc to A tile row = lane
    {
        float* row = sA + lane * SA_STRIDE;
#pragma unroll
        for (int j = 0; j < 9; j++)
            *(float4*)(row + 4 * j) =
                make_float4(enc[4 * j], enc[4 * j + 1], enc[4 * j + 2], enc[4 * j + 3]);
        *(float4*)(row + 36) = make_float4(0.f, 0.f, 0.f, 0.f);
    }
    __syncthreads();   // weights staged by whole block (A tiles are warp-private)

    // -------- layer 1: K=40, N=64 --------
    {
        float C[2][8][4];
        mma_layer<5, 8>(smf + B1_F, sA, C, lane);
        __syncwarp();
        store_relu<8>(sA, C, lane);
        __syncwarp();
    }
    // -------- layer 2: K=64, N=64 --------
    {
        float C[2][8][4];
        mma_layer<8, 8>(smf + B2_F, sA, C, lane);
        __syncwarp();
        store_relu<8>(sA, C, lane);
        __syncwarp();
    }
    // -------- layer 3: K=64, N=8 (3 valid) --------
    {
        float C[2][1][4];
        mma_layer<8, 1>(smf + B3_F, sA, C, lane);

        const int g = lane >> 2, c = lane & 3;
#pragma unroll
        for (int mt = 0; mt < 2; mt++) {
            int r0 = mt * 16 + g;
            int pa = __shfl_sync(0xFFFFFFFFu, pid, r0);
            int pb = __shfl_sync(0xFFFFFFFFu, pid, r0 + 8);
            if (c == 0) {
                out[pa * 3 + 0] = C[mt][0][0];
                out[pa * 3 + 1] = C[mt][0][1];
                out[pb * 3 + 0] = C[mt][0][2];
                out[pb * 3 + 1] = C[mt][0][3];
            } else if (c == 1) {
                out[pa * 3 + 2] = C[mt][0][0];
                out[pb * 3 + 2] = C[mt][0][2];
            }
        }
    }
}

extern "C" void kernel_launch(void* const* d_in, const int* in_sizes, int n_in,
                              void* d_out, int out_size)
{
    const float* x      = (const float*)d_in[0];
    const float* tables = (const float*)d_in[1];
    const float* w1     = (const float*)d_in[2];
    const float* w2     = (const float*)d_in[3];
    const float* w3     = (const float*)d_in[4];

    const int npts = in_sizes[0] / 2;

    LevelParams lp;
    for (int l = 0; l < NLVL; l++) {
        int res = (int)floor(16.0 * pow(1.3819, (double)l));
        lp.resf[l]  = (float)res;
        lp.res1[l]  = res + 1;
        long long dsz = (long long)(res + 1) * (long long)(res + 1);
        lp.dense[l] = (dsz <= (long long)TSIZE) ? 1 : 0;
    }

    cudaFuncSetAttribute(videohash_kernel,
                         cudaFuncAttributeMaxDynamicSharedMemorySize, SMEM_BYTES);

    const int nq = (npts + 3) / 4;
    const int nbq = (nq + 255) / 256;

    setup_kernel<<<256 + (WPACKF + 255) / 256, 256>>>(w1, w2, w3);
    hist_kernel<<<nbq, 256>>>((const float4*)x, npts);
    scan_kernel<<<1, 1024>>>();
    scatter_kernel<<<nbq, 256>>>((const float4*)x, npts);

    int blocks = (npts + 255) / 256;
    videohash_kernel<<<blocks, 256, SMEM_BYTES>>>((const float2*)x, (const float2*)tables,
                                                  (float*)d_out, npts, lp);
}

// round 12
// speedup vs baseline: 1.2485x; 1.1688x over previous
#include <cuda_runtime.h>
#include <math.h>
#include <stdint.h>

#define NLVL 16
#define TSIZE (1u << 19)
#define TMASK (TSIZE - 1u)
#define HPRIME 2654435761u

#define NPTS_MAX 2097152
#define NBUCK 65536

__device__ uint32_t g_hist[NBUCK];
__device__ uint32_t g_cursor[NBUCK];
__device__ uint32_t g_bsum[256];
__device__ uint32_t g_perm[NPTS_MAX];

// fragment-packed tf32-rounded weights: L1 40x64 (5kt x 8nt), L2 64x64 (8x8), L3 64x8 (8x1)
#define B1_F 0
#define B2_F 2560
#define B3_F 6656
#define WPACKF 7168
__device__ float g_wfrag[WPACKF];

#define SA_STRIDE 68
#define SA_BASE 7168
#define NWARP 8
#define SMEM_FLOATS (SA_BASE + NWARP * 32 * SA_STRIDE)   // 24576
#define SMEM_BYTES (SMEM_FLOATS * 4)

struct LevelParams {
    float resf[NLVL];
    int   res1[NLVL];
    int   dense[NLVL];
};

// ---------------- Morton helpers ----------------
__device__ __forceinline__ uint32_t part1by1(uint32_t x) {
    x &= 0xFFu;
    x = (x | (x << 4)) & 0x0F0Fu;
    x = (x | (x << 2)) & 0x3333u;
    x = (x | (x << 1)) & 0x5555u;
    return x;
}
__device__ __forceinline__ uint32_t bucket_code(float px, float py) {
    int bx = (int)(px * 256.0f); bx = bx < 0 ? 0 : (bx > 255 ? 255 : bx);
    int by = (int)(py * 256.0f); by = by < 0 ? 0 : (by > 255 ? 255 : by);
    return part1by1((uint32_t)bx) | (part1by1((uint32_t)by) << 1);
}

// ---------------- fused setup: zero hist + pack tf32 weights ----------------
__global__ void setup_kernel(const float* __restrict__ w1,
                             const float* __restrict__ w2,
                             const float* __restrict__ w3) {
    int b = blockIdx.x;
    int t = threadIdx.x;
    if (b < 256) {
        g_hist[b * 256 + t] = 0u;
        return;
    }
    int e = (b - 256) * 256 + t;
    if (e >= WPACKF) return;
    int base, NT, rel;
    const float* W; int ncols; int kmax;
    if (e < B2_F)      { base = B1_F; NT = 8; rel = e - B1_F; W = w1; ncols = 64; kmax = 34; }
    else if (e < B3_F) { base = B2_F; NT = 8; rel = e - B2_F; W = w2; ncols = 64; kmax = 64; }
    else               { base = B3_F; NT = 1; rel = e - B3_F; W = w3; ncols = 3;  kmax = 64; }
    int tile = rel >> 6;
    int r    = rel & 63;
    int lane = r >> 1, sel = r & 1;
    int kt = tile / NT, nt = tile % NT;
    int k = kt * 8 + (lane & 3) + sel * 4;
    int n = nt * 8 + (lane >> 2);
    float v = 0.0f;
    if (k < kmax && n < ncols) v = W[k * ncols + n];
    uint32_t hb;
    asm("cvt.rna.tf32.f32 %0, %1;" : "=r"(hb) : "f"(v));
    g_wfrag[e] = __uint_as_float(hb);
}

// ---------------- hist (4 pts per thread) ----------------
__global__ void hist_kernel(const float4* __restrict__ xin4, int npts) {
    int t = blockIdx.x * 256 + threadIdx.x;
    int i0 = t * 4;
    if (i0 >= npts) return;
    float4 a = __ldg(xin4 + t * 2);
    float4 b = __ldg(xin4 + t * 2 + 1);
    atomicAdd(&g_hist[bucket_code(a.x, a.y)], 1u);
    if (i0 + 1 < npts) atomicAdd(&g_hist[bucket_code(a.z, a.w)], 1u);
    if (i0 + 2 < npts) atomicAdd(&g_hist[bucket_code(b.x, b.y)], 1u);
    if (i0 + 3 < npts) atomicAdd(&g_hist[bucket_code(b.z, b.w)], 1u);
}

// ---------------- 3-stage parallel scan: hist -> cursor (exclusive) ----------------
// stage A: each of 256 blocks scans its 256 elements; writes local-exclusive into
//          g_cursor and its block total into g_bsum.
__global__ __launch_bounds__(256) void scanA_kernel() {
    __shared__ uint32_t sh[256];
    const int b = blockIdx.x, t = threadIdx.x;
    uint32_t v = g_hist[b * 256 + t];
    sh[t] = v;
    __syncthreads();
    // Hillis-Steele inclusive on 256
    for (int d = 1; d < 256; d <<= 1) {
        uint32_t u = (t >= d) ? sh[t - d] : 0u;
        __syncthreads();
        sh[t] += u;
        __syncthreads();
    }
    g_cursor[b * 256 + t] = sh[t] - v;          // local exclusive
    if (t == 255) g_bsum[b] = sh[255];          // block total
}
// stage B: single block scans 256 block sums into exclusive offsets (in place).
__global__ __launch_bounds__(256) void scanB_kernel() {
    __shared__ uint32_t sh[256];
    const int t = threadIdx.x;
    uint32_t v = g_bsum[t];
    sh[t] = v;
    __syncthreads();
    for (int d = 1; d < 256; d <<= 1) {
        uint32_t u = (t >= d) ? sh[t - d] : 0u;
        __syncthreads();
        sh[t] += u;
        __syncthreads();
    }
    g_bsum[t] = sh[t] - v;                      // exclusive block offset
}
// stage C: add block offsets.
__global__ __launch_bounds__(256) void scanC_kernel() {
    const int b = blockIdx.x, t = threadIdx.x;
    g_cursor[b * 256 + t] += g_bsum[b];
}

// ---------------- scatter (4 pts per thread) ----------------
__global__ void scatter_kernel(const float4* __restrict__ xin4, int npts) {
    int t = blockIdx.x * 256 + threadIdx.x;
    int i0 = t * 4;
    if (i0 >= npts) return;
    float4 a = __ldg(xin4 + t * 2);
    float4 b = __ldg(xin4 + t * 2 + 1);
    uint32_t s0 = atomicAdd(&g_cursor[bucket_code(a.x, a.y)], 1u);
    g_perm[s0] = (uint32_t)i0;
    if (i0 + 1 < npts) { uint32_t s = atomicAdd(&g_cursor[bucket_code(a.z, a.w)], 1u); g_perm[s] = (uint32_t)(i0 + 1); }
    if (i0 + 2 < npts) { uint32_t s = atomicAdd(&g_cursor[bucket_code(b.x, b.y)], 1u); g_perm[s] = (uint32_t)(i0 + 2); }
    if (i0 + 3 < npts) { uint32_t s = atomicAdd(&g_cursor[bucket_code(b.z, b.w)], 1u); g_perm[s] = (uint32_t)(i0 + 3); }
}

// ---------------- mma helpers ----------------
__device__ __forceinline__ void cvt_hilo(float v, uint32_t& h, uint32_t& l) {
    uint32_t hb;
    asm("cvt.rna.tf32.f32 %0, %1;" : "=r"(hb) : "f"(v));
    h = hb;
    l = __float_as_uint(v - __uint_as_float(hb));
}
__device__ __forceinline__ void mma8(float c[4], const uint32_t a[4], const uint32_t b[2]) {
    asm volatile("mma.sync.aligned.m16n8k8.row.col.f32.tf32.tf32.f32 "
        "{%0,%1,%2,%3}, {%4,%5,%6,%7}, {%8,%9}, {%0,%1,%2,%3};"
        : "+f"(c[0]), "+f"(c[1]), "+f"(c[2]), "+f"(c[3])
        : "r"(a[0]), "r"(a[1]), "r"(a[2]), "r"(a[3]), "r"(b[0]), "r"(b[1]));
}

template<int KT, int NT>
__device__ __forceinline__ void mma_layer(const float* __restrict__ sB,
                                          const float* __restrict__ sA,
                                          float C[2][NT][4], int lane) {
    const int g = lane >> 2, c = lane & 3;
#pragma unroll
    for (int mt = 0; mt < 2; mt++)
#pragma unroll
        for (int nt = 0; nt < NT; nt++)
#pragma unroll
            for (int r = 0; r < 4; r++) C[mt][nt][r] = 0.0f;

#pragma unroll 1
    for (int kt = 0; kt < KT; kt++) {
        uint32_t Bh[NT][2];
#pragma unroll
        for (int nt = 0; nt < NT; nt++) {
            float2 bv = *(const float2*)(sB + (kt * NT + nt) * 64 + lane * 2);
            Bh[nt][0] = __float_as_uint(bv.x);   // pre-rounded tf32
            Bh[nt][1] = __float_as_uint(bv.y);
        }
#pragma unroll
        for (int mt = 0; mt < 2; mt++) {
            const float* ar = sA + (mt * 16 + g) * SA_STRIDE + kt * 8;
            uint32_t Ah[4], Al[4];
            cvt_hilo(ar[c],                     Ah[0], Al[0]);
            cvt_hilo(ar[8 * SA_STRIDE + c],     Ah[1], Al[1]);
            cvt_hilo(ar[c + 4],                 Ah[2], Al[2]);
            cvt_hilo(ar[8 * SA_STRIDE + c + 4], Ah[3], Al[3]);
#pragma unroll
            for (int nt = 0; nt < NT; nt++) {
                mma8(C[mt][nt], Ah, Bh[nt]);
                mma8(C[mt][nt], Al, Bh[nt]);
            }
        }
    }
}

template<int NT>
__device__ __forceinline__ void store_relu(float* __restrict__ sA,
                                           float C[2][NT][4], int lane) {
    const int g = lane >> 2, c = lane & 3;
#pragma unroll
    for (int mt = 0; mt < 2; mt++)
#pragma unroll
        for (int nt = 0; nt < NT; nt++) {
            float* p = sA + (mt * 16 + g) * SA_STRIDE + nt * 8 + 2 * c;
            *(float2*)p = make_float2(fmaxf(C[mt][nt][0], 0.f), fmaxf(C[mt][nt][1], 0.f));
            *(float2*)(p + 8 * SA_STRIDE) =
                make_float2(fmaxf(C[mt][nt][2], 0.f), fmaxf(C[mt][nt][3], 0.f));
        }
}

// ---------------- main fused kernel (exact R6 form) ----------------
__global__ __launch_bounds__(256, 2)
void videohash_kernel(const float2* __restrict__ xin,
                      const float2* __restrict__ tables,
                      float* __restrict__ out,
                      int npts, LevelParams lp)
{
    extern __shared__ float smf[];

    const int tid  = threadIdx.x;
    const int warp = tid >> 5;
    const int lane = tid & 31;
    float* sA = smf + SA_BASE + warp * (32 * SA_STRIDE);

    // stage weights to SMEM (coalesced, 7 float4 per thread)
    {
        const float4* src = (const float4*)g_wfrag;
        float4* dst = (float4*)smf;
#pragma unroll
        for (int i = 0; i < 7; i++) dst[i * 256 + tid] = src[i * 256 + tid];
    }

    int slot = blockIdx.x * 256 + tid;
    if (slot >= npts) slot = npts - 1;
    const int pid = (int)g_perm[slot];
    const float2 p = __ldg(xin + pid);

    // -------- encode --------
    float enc[36];
    enc[0] = p.x; enc[1] = p.y; enc[34] = 0.f; enc[35] = 0.f;
#pragma unroll
    for (int l = 0; l < NLVL; l++) {
        const float rf = lp.resf[l];
        float px = p.x * rf, py = p.y * rf;
        float fx = floorf(px), fy = floorf(py);
        float wx = px - fx, wy = py - fy;
        unsigned X = (unsigned)fx, Y = (unsigned)fy;
        const float2* tab = tables + (size_t)l * TSIZE;
        unsigned i00, i10, i01, i11;
        if (lp.dense[l]) {
            unsigned r1 = (unsigned)lp.res1[l];
            unsigned b = X + Y * r1;
            i00 = b; i10 = b + 1u; i01 = b + r1; i11 = b + r1 + 1u;
        } else {
            unsigned hy = Y * HPRIME, hy1 = (Y + 1u) * HPRIME;
            i00 = (X ^ hy)  & TMASK; i10 = ((X + 1u) ^ hy)  & TMASK;
            i01 = (X ^ hy1) & TMASK; i11 = ((X + 1u) ^ hy1) & TMASK;
        }
        float2 f00 = __ldg(tab + i00), f10 = __ldg(tab + i10);
        float2 f01 = __ldg(tab + i01), f11 = __ldg(tab + i11);
        float w00 = (1.f - wx) * (1.f - wy), w10 = wx * (1.f - wy);
        float w01 = (1.f - wx) * wy,         w11 = wx * wy;
        enc[2 + 2 * l]     = f00.x * w00 + f10.x * w10 + f01.x * w01 + f11.x * w11;
        enc[2 + 2 * l + 1] = f00.y * w00 + f10.y * w10 + f01.y * w01 + f11.y * w11;
    }

    // stage enc to A tile row = lane
    {
        float* row = sA + lane * SA_STRIDE;
#pragma unroll
        for (int j = 0; j < 9; j++)
            *(float4*)(row + 4 * j) =
                make_float4(enc[4 * j], enc[4 * j + 1], enc[4 * j + 2], enc[4 * j + 3]);
        *(float4*)(row + 36) = make_float4(0.f, 0.f, 0.f, 0.f);
    }
    __syncthreads();   // weights staged by whole block (A tiles are warp-private)

    // -------- layer 1: K=40, N=64 --------
    {
        float C[2][8][4];
        mma_layer<5, 8>(smf + B1_F, sA, C, lane);
        __syncwarp();
        store_relu<8>(sA, C, lane);
        __syncwarp();
    }
    // -------- layer 2: K=64, N=64 --------
    {
        float C[2][8][4];
        mma_layer<8, 8>(smf + B2_F, sA, C, lane);
        __syncwarp();
        store_relu<8>(sA, C, lane);
        __syncwarp();
    }
    // -------- layer 3: K=64, N=8 (3 valid) --------
    {
        float C[2][1][4];
        mma_layer<8, 1>(smf + B3_F, sA, C, lane);

        const int g = lane >> 2, c = lane & 3;
#pragma unroll
        for (int mt = 0; mt < 2; mt++) {
            int r0 = mt * 16 + g;
            int pa = __shfl_sync(0xFFFFFFFFu, pid, r0);
            int pb = __shfl_sync(0xFFFFFFFFu, pid, r0 + 8);
            if (c == 0) {
                out[pa * 3 + 0] = C[mt][0][0];
                out[pa * 3 + 1] = C[mt][0][1];
                out[pb * 3 + 0] = C[mt][0][2];
                out[pb * 3 + 1] = C[mt][0][3];
            } else if (c == 1) {
                out[pa * 3 + 2] = C[mt][0][0];
                out[pb * 3 + 2] = C[mt][0][2];
            }
        }
    }
}

extern "C" void kernel_launch(void* const* d_in, const int* in_sizes, int n_in,
                              void* d_out, int out_size)
{
    const float* x      = (const float*)d_in[0];
    const float* tables = (const float*)d_in[1];
    const float* w1     = (const float*)d_in[2];
    const float* w2     = (const float*)d_in[3];
    const float* w3     = (const float*)d_in[4];

    const int npts = in_sizes[0] / 2;

    LevelParams lp;
    for (int l = 0; l < NLVL; l++) {
        int res = (int)floor(16.0 * pow(1.3819, (double)l));
        lp.resf[l]  = (float)res;
        lp.res1[l]  = res + 1;
        long long dsz = (long long)(res + 1) * (long long)(res + 1);
        lp.dense[l] = (dsz <= (long long)TSIZE) ? 1 : 0;
    }

    cudaFuncSetAttribute(videohash_kernel,
                         cudaFuncAttributeMaxDynamicSharedMemorySize, SMEM_BYTES);

    const int nq = (npts + 3) / 4;
    const int nbq = (nq + 255) / 256;

    setup_kernel<<<256 + (WPACKF + 255) / 256, 256>>>(w1, w2, w3);
    hist_kernel<<<nbq, 256>>>((const float4*)x, npts);
    scanA_kernel<<<256, 256>>>();
    scanB_kernel<<<1, 256>>>();
    scanC_kernel<<<256, 256>>>();
    scatter_kernel<<<nbq, 256>>>((const float4*)x, npts);

    int blocks = (npts + 255) / 256;
    videohash_kernel<<<blocks, 256, SMEM_BYTES>>>((const float2*)x, (const float2*)tables,
                                                  (float*)d_out, npts, lp);
}